// round 2
// baseline (speedup 1.0000x reference)
#include <cuda_runtime.h>
#include <cuda_bf16.h>
#include <cstdint>

#define T_STEPS 16384
#define F_IN    2048
#define HD      16
#define GD      48
#define LN      6
#define AD      64

// scratch for precomputed layer-0 input projection (gi0 = x @ W_ih0^T + b_ih0)
__device__ float g_GI0[T_STEPS * GD];

// pair tables for attention energies: 20 (i,l) pairs, i=0..4, l=i..5
__constant__ int c_PI[20] = {0,0,0,0,0,0, 1,1,1,1,1, 2,2,2,2, 3,3,3, 4,4};
__constant__ int c_PL[20] = {0,1,2,3,4,5, 1,2,3,4,5, 2,3,4,5, 3,4,5, 4,5};

__device__ __forceinline__ float sigmoidf_fast(float x) {
    return __fdividef(1.f, 1.f + __expf(-x));
}
__device__ __forceinline__ float tanhf_fast(float x) {
    float ax = fabsf(x);
    float e  = __expf(-2.f * ax);
    float r  = __fdividef(1.f - e, 1.f + e);
    return copysignf(r, x);
}

__device__ __forceinline__ void cp_async16(void* smem_dst, const void* gsrc) {
    unsigned sa = (unsigned)__cvta_generic_to_shared(smem_dst);
    asm volatile("cp.async.ca.shared.global [%0], [%1], 16;\n" :: "r"(sa), "l"(gsrc));
}

// ---------------------------------------------------------------------------
// Kernel 1: GI0[t][g] = b_ih0[g] + sum_f batch[t][f] * W_ih0[g][f]
// M=16384, N=48, K=2048 GEMM, tiled. 512 blocks x 256 threads.
// ---------------------------------------------------------------------------
__global__ __launch_bounds__(256) void k_gi0(
    const float* __restrict__ batch,
    const float* __restrict__ Wih0,
    const float* __restrict__ bih0)
{
    __shared__ float Bs[32 * 65];
    __shared__ float Ws[48 * 64];
    const int t0  = blockIdx.x * 32;
    const int tid = threadIdx.x;
    const int tl  = tid & 31;
    const int gg  = tid >> 5;      // 0..7
    const int g0  = gg * 6;

    float acc[6];
#pragma unroll
    for (int j = 0; j < 6; j++) acc[j] = 0.f;

    for (int k0 = 0; k0 < F_IN; k0 += 64) {
        __syncthreads();
#pragma unroll
        for (int i = 0; i < 8; i++) {          // 32x64 batch tile
            int idx = tid + i * 256;
            int r = idx >> 6, c = idx & 63;
            Bs[r * 65 + c] = batch[(t0 + r) * F_IN + k0 + c];
        }
#pragma unroll
        for (int i = 0; i < 12; i++) {         // 48x64 weight tile
            int idx = tid + i * 256;
            int r = idx >> 6, c = idx & 63;
            Ws[r * 64 + c] = Wih0[r * F_IN + k0 + c];
        }
        __syncthreads();
#pragma unroll 4
        for (int kk = 0; kk < 64; kk++) {
            float b = Bs[tl * 65 + kk];
#pragma unroll
            for (int j = 0; j < 6; j++) acc[j] += b * Ws[(g0 + j) * 64 + kk];
        }
    }
#pragma unroll
    for (int j = 0; j < 6; j++)
        g_GI0[(t0 + tl) * GD + g0 + j] = acc[j] + bih0[g0 + j];
}

// ---------------------------------------------------------------------------
// Kernel 2: persistent single-block sequential scan over T steps.
// ---------------------------------------------------------------------------
struct Smem {
    float gi0[2 * GD];          // double-buffered prefetch of GI0 row (16B aligned @0)
    float Wih[5 * 48 * 17];     // layers 1..5, row-padded to 17
    float Whh[6 * 48 * 17];     // layer 0 + layers 1..5, row-padded
    float Wa [6 * 16 * 64];
    float ba [6 * 64];
    float va [6 * 64];
    float bih[5 * 48];
    float bhh[6 * 48];
    float fc1[32 * 17];         // padded
    float fc1b[32];
    float fc2[32];
    float h   [6 * 16];         // carried hidden state
    float newS[6 * 16];         // this step's GRU outputs
    float gh  [6 * 48];         // precomputed h @ Whh^T + b_hh
    float e   [36];             // energies e[i*6+l]
    float fc2b;
};

__global__ __launch_bounds__(256, 1) void k_scan(
    const float* __restrict__ h0,
    const float* __restrict__ W_hh0,
    const float* __restrict__ b_hh0,
    const float* __restrict__ W_ih,
    const float* __restrict__ W_hh,
    const float* __restrict__ b_ih,
    const float* __restrict__ b_hh,
    const float* __restrict__ Wa,
    const float* __restrict__ ba,
    const float* __restrict__ va,
    const float* __restrict__ fc1_w,
    const float* __restrict__ fc1_b,
    const float* __restrict__ fc2_w,
    const float* __restrict__ fc2_b,
    float* __restrict__ out)
{
    extern __shared__ char smem_raw[];
    Smem* s = reinterpret_cast<Smem*>(smem_raw);

    const int tid  = threadIdx.x;
    const int warp = tid >> 5;
    const int lane = tid & 31;

    // ---- load all weights into shared (once) ----
    for (int idx = tid; idx < 5 * 48 * 16; idx += 256) {       // Wih (pad 17)
        int row = idx >> 4, hh = idx & 15;
        s->Wih[row * 17 + hh] = W_ih[idx];
    }
    for (int idx = tid; idx < 48 * 16; idx += 256) {           // Whh layer 0
        int row = idx >> 4, hh = idx & 15;
        s->Whh[row * 17 + hh] = W_hh0[idx];
    }
    for (int idx = tid; idx < 5 * 48 * 16; idx += 256) {       // Whh layers 1..5
        int row = idx >> 4, hh = idx & 15;
        s->Whh[(48 + row) * 17 + hh] = W_hh[idx];
    }
    for (int idx = tid; idx < 6 * 16 * 64; idx += 256) s->Wa[idx] = Wa[idx];
    for (int idx = tid; idx < 6 * 64; idx += 256) { s->ba[idx] = ba[idx]; s->va[idx] = va[idx]; }
    for (int idx = tid; idx < 5 * 48; idx += 256) s->bih[idx] = b_ih[idx];
    for (int idx = tid; idx < 48; idx += 256) s->bhh[idx] = b_hh0[idx];
    for (int idx = tid; idx < 5 * 48; idx += 256) s->bhh[48 + idx] = b_hh[idx];
    for (int idx = tid; idx < 32 * 16; idx += 256) {
        int row = idx >> 4, hh = idx & 15;
        s->fc1[row * 17 + hh] = fc1_w[idx];
    }
    if (tid < 32) { s->fc1b[tid] = fc1_b[tid]; s->fc2[tid] = fc2_w[tid]; }
    if (tid == 0) s->fc2b = fc2_b[0];
    for (int idx = tid; idx < 6 * 16; idx += 256) s->h[idx] = h0[idx];
    __syncthreads();

    // ---- initial gh from h0 ----
    if (warp < LN) {
        const int i = warp;
        float hv[16];
#pragma unroll
        for (int hh = 0; hh < 16; hh++) hv[hh] = s->h[i * 16 + hh];
        const float* w = &s->Whh[i * 48 * 17];
        {
            int row = lane;
            float acc = s->bhh[i * 48 + row];
#pragma unroll
            for (int hh = 0; hh < 16; hh++) acc += hv[hh] * w[row * 17 + hh];
            s->gh[i * 48 + row] = acc;
        }
        if (lane < 16) {
            int row = 32 + lane;
            float acc = s->bhh[i * 48 + row];
#pragma unroll
            for (int hh = 0; hh < 16; hh++) acc += hv[hh] * w[row * 17 + hh];
            s->gh[i * 48 + row] = acc;
        }
    }
    // prefetch gi0 row for t=0
    if (warp == 0) {
        if (lane < 12) cp_async16(&s->gi0[0 + lane * 4], &g_GI0[0 + lane * 4]);
        asm volatile("cp.async.commit_group;\n");
    }
    __syncthreads();

    // =========================== time loop ===========================
    for (int t = 0; t < T_STEPS; t++) {
        // ---------- Phase A: serial GRU chain (warp 0) ----------
        if (warp == 0) {
            // prefetch next step's gi0 row, then wait for current row
            if (lane < 12 && (t + 1) < T_STEPS)
                cp_async16(&s->gi0[((t + 1) & 1) * GD + lane * 4],
                           &g_GI0[(t + 1) * GD + lane * 4]);
            asm volatile("cp.async.commit_group;\n");
            asm volatile("cp.async.wait_group 1;\n");
            __syncwarp();

            const float* gi0 = &s->gi0[(t & 1) * GD];
            // layer 0 (gi precomputed, includes b_ih0)
            if (lane < 16) {
                const int j = lane;
                float ar = gi0[j], az = gi0[16 + j], an = gi0[32 + j];
                float r = sigmoidf_fast(ar + s->gh[j]);
                float z = sigmoidf_fast(az + s->gh[16 + j]);
                float n = tanhf_fast(an + r * s->gh[32 + j]);
                s->newS[j] = (1.f - z) * n + z * s->h[j];
            }
            __syncwarp();
            // layers 1..5
            for (int l = 1; l < LN; l++) {
                float inp[16];
#pragma unroll
                for (int hh = 0; hh < 16; hh++) inp[hh] = s->newS[(l - 1) * 16 + hh];
                if (lane < 16) {
                    const int j = lane;
                    const float* w = &s->Wih[(l - 1) * 48 * 17];
                    float ar = s->bih[(l - 1) * 48 + j];
                    float az = s->bih[(l - 1) * 48 + 16 + j];
                    float an = s->bih[(l - 1) * 48 + 32 + j];
#pragma unroll
                    for (int hh = 0; hh < 16; hh++) {
                        ar += inp[hh] * w[j * 17 + hh];
                        az += inp[hh] * w[(16 + j) * 17 + hh];
                        an += inp[hh] * w[(32 + j) * 17 + hh];
                    }
                    float r = sigmoidf_fast(ar + s->gh[l * 48 + j]);
                    float z = sigmoidf_fast(az + s->gh[l * 48 + 16 + j]);
                    float n = tanhf_fast(an + r * s->gh[l * 48 + 32 + j]);
                    s->newS[l * 16 + j] = (1.f - z) * n + z * s->h[l * 16 + j];
                }
                __syncwarp();
            }
        }
        __syncthreads();

        // ---------- Phase B: attention energies (all warps) + FC head ----------
        for (int p = warp; p < 20; p += 8) {
            const int i = c_PI[p], l = c_PL[p];
            const int a0 = lane, a1 = lane + 32;
            float acc0 = s->ba[i * 64 + a0];
            float acc1 = s->ba[i * 64 + a1];
            const float* wa = &s->Wa[i * 16 * 64];
#pragma unroll
            for (int hh = 0; hh < 16; hh++) {
                float sv = s->newS[l * 16 + hh];
                acc0 += sv * wa[hh * 64 + a0];
                acc1 += sv * wa[hh * 64 + a1];
            }
            float v = tanhf_fast(acc0) * s->va[i * 64 + a0]
                    + tanhf_fast(acc1) * s->va[i * 64 + a1];
#pragma unroll
            for (int off = 16; off; off >>= 1)
                v += __shfl_xor_sync(0xffffffffu, v, off);
            if (lane == 0) s->e[i * 6 + l] = v;
        }
        if (warp == 7) {
            // out[t] = fc2 . (fc1 . newS[5] + b1) + b2   (h_next[5]==newS[5])
            float acc = s->fc1b[lane];
#pragma unroll
            for (int hh = 0; hh < 16; hh++)
                acc += s->newS[5 * 16 + hh] * s->fc1[lane * 17 + hh];
            acc *= s->fc2[lane];
#pragma unroll
            for (int off = 16; off; off >>= 1)
                acc += __shfl_xor_sync(0xffffffffu, acc, off);
            if (lane == 0) out[t] = acc + s->fc2b;
        }
        __syncthreads();

        // ---------- Phase C: softmax combine -> h_next, then gh precompute ----------
        if (warp < LN) {
            const int i = warp;
            if (i < 5) {
                const int k = 6 - i;
                float ev[6], wv[6];
                float m = -1e30f;
                for (int q = 0; q < k; q++) {
                    ev[q] = s->e[i * 6 + (i + q)];
                    m = fmaxf(m, ev[q]);
                }
                float ssum = 0.f;
                for (int q = 0; q < k; q++) { wv[q] = __expf(ev[q] - m); ssum += wv[q]; }
                float inv = __fdividef(1.f, ssum);
                if (lane < 16) {
                    float acc = 0.f;
                    for (int q = 0; q < k; q++)
                        acc += wv[q] * s->newS[(i + q) * 16 + lane];
                    s->h[i * 16 + lane] = acc * inv;
                }
            } else {
                if (lane < 16) s->h[5 * 16 + lane] = s->newS[5 * 16 + lane];
            }
            __syncwarp();
            // gh[i] = h[i] @ Whh[i]^T + bhh[i]
            float hv[16];
#pragma unroll
            for (int hh = 0; hh < 16; hh++) hv[hh] = s->h[i * 16 + hh];
            const float* w = &s->Whh[i * 48 * 17];
            {
                int row = lane;
                float acc = s->bhh[i * 48 + row];
#pragma unroll
                for (int hh = 0; hh < 16; hh++) acc += hv[hh] * w[row * 17 + hh];
                s->gh[i * 48 + row] = acc;
            }
            if (lane < 16) {
                int row = 32 + lane;
                float acc = s->bhh[i * 48 + row];
#pragma unroll
                for (int hh = 0; hh < 16; hh++) acc += hv[hh] * w[row * 17 + hh];
                s->gh[i * 48 + row] = acc;
            }
        }
        __syncthreads();
    }
}

// ---------------------------------------------------------------------------
extern "C" void kernel_launch(void* const* d_in, const int* in_sizes, int n_in,
                              void* d_out, int out_size)
{
    const float* batch  = (const float*)d_in[0];
    const float* h0     = (const float*)d_in[1];
    const float* W_ih0  = (const float*)d_in[2];
    const float* W_hh0  = (const float*)d_in[3];
    const float* b_ih0  = (const float*)d_in[4];
    const float* b_hh0  = (const float*)d_in[5];
    const float* W_ih   = (const float*)d_in[6];
    const float* W_hh   = (const float*)d_in[7];
    const float* b_ih   = (const float*)d_in[8];
    const float* b_hh   = (const float*)d_in[9];
    const float* Wa     = (const float*)d_in[10];
    const float* ba     = (const float*)d_in[11];
    const float* va     = (const float*)d_in[12];
    const float* fc1_w  = (const float*)d_in[13];
    const float* fc1_b  = (const float*)d_in[14];
    const float* fc2_w  = (const float*)d_in[15];
    const float* fc2_b  = (const float*)d_in[16];
    float* out = (float*)d_out;

    cudaFuncSetAttribute(k_scan, cudaFuncAttributeMaxDynamicSharedMemorySize,
                         (int)sizeof(Smem));

    k_gi0<<<T_STEPS / 32, 256>>>(batch, W_ih0, b_ih0);
    k_scan<<<1, 256, sizeof(Smem)>>>(h0, W_hh0, b_hh0, W_ih, W_hh, b_ih, b_hh,
                                     Wa, ba, va, fc1_w, fc1_b, fc2_w, fc2_b, out);
}

// round 3
// speedup vs baseline: 1.0923x; 1.0923x over previous
#include <cuda_runtime.h>
#include <cuda_bf16.h>
#include <cstdint>

#define T_STEPS 16384
#define F_IN    2048
#define HD      16
#define GD      48
#define LN      6
#define AD      64

// scratch for precomputed layer-0 input projection (gi0 = x @ W_ih0^T + b_ih0)
__device__ float g_GI0[T_STEPS * GD];

// Early energy pairs (l <= 2): run concurrently with GRU layers 3..5
__constant__ int c_PIE[6] = {0, 0, 1, 0, 1, 2};
__constant__ int c_PLE[6] = {0, 1, 1, 2, 2, 2};
// Late energy pairs (l in {3,4,5}), 14 pairs on warps 1..7 (2 each)
__constant__ int c_PIL[14] = {0,1,2,3, 0,1,2,3,4, 0,1,2,3,4};
__constant__ int c_PLL[14] = {3,3,3,3, 4,4,4,4,4, 5,5,5,5,5};

__device__ __forceinline__ float sigmoidf_fast(float x) {
    return __fdividef(1.f, 1.f + __expf(-x));
}
__device__ __forceinline__ float tanhf_fast(float x) {
    float ax = fabsf(x);
    float e  = __expf(-2.f * ax);
    float r  = __fdividef(1.f - e, 1.f + e);
    return copysignf(r, x);
}

__device__ __forceinline__ void cp_async16(void* smem_dst, const void* gsrc) {
    unsigned sa = (unsigned)__cvta_generic_to_shared(smem_dst);
    asm volatile("cp.async.ca.shared.global [%0], [%1], 16;\n" :: "r"(sa), "l"(gsrc));
}

// ---------------------------------------------------------------------------
// Kernel 1: GI0[t][g] = b_ih0[g] + sum_f batch[t][f] * W_ih0[g][f]
// ---------------------------------------------------------------------------
__global__ __launch_bounds__(256) void k_gi0(
    const float* __restrict__ batch,
    const float* __restrict__ Wih0,
    const float* __restrict__ bih0)
{
    __shared__ float Bs[32 * 65];
    __shared__ float Ws[48 * 64];
    const int t0  = blockIdx.x * 32;
    const int tid = threadIdx.x;
    const int tl  = tid & 31;
    const int gg  = tid >> 5;      // 0..7
    const int g0  = gg * 6;

    float acc[6];
#pragma unroll
    for (int j = 0; j < 6; j++) acc[j] = 0.f;

    for (int k0 = 0; k0 < F_IN; k0 += 64) {
        __syncthreads();
#pragma unroll
        for (int i = 0; i < 8; i++) {
            int idx = tid + i * 256;
            int r = idx >> 6, c = idx & 63;
            Bs[r * 65 + c] = batch[(t0 + r) * F_IN + k0 + c];
        }
#pragma unroll
        for (int i = 0; i < 12; i++) {
            int idx = tid + i * 256;
            int r = idx >> 6, c = idx & 63;
            Ws[r * 64 + c] = Wih0[r * F_IN + k0 + c];
        }
        __syncthreads();
#pragma unroll 4
        for (int kk = 0; kk < 64; kk++) {
            float b = Bs[tl * 65 + kk];
#pragma unroll
            for (int j = 0; j < 6; j++) acc[j] += b * Ws[(g0 + j) * 64 + kk];
        }
    }
#pragma unroll
    for (int j = 0; j < 6; j++)
        g_GI0[(t0 + tl) * GD + g0 + j] = acc[j] + bih0[g0 + j];
}

// ---------------------------------------------------------------------------
// Kernel 2: persistent single-block sequential scan.
// ---------------------------------------------------------------------------
#define RP 20   // row pad (floats) => 80B stride, LDS.128-friendly & conflict-free

struct Smem {
    float gi0 [2 * GD];              // double-buffered GI0 row
    float WihA[5 * GD * RP];         // layers 1..5, rows padded to RP
    float WhhA[6 * GD * RP];         // layer 0..5, rows padded
    float Wa  [6 * 16 * 64];
    float ba  [6 * 64];
    float va  [6 * 64];
    float bihA[5 * GD];              // layers 1..5 b_ih
    float bhhA[6 * GD];
    float fc1A[32 * RP];
    float fc1b[32];
    float fc2 [32];
    float h   [6 * 16];
    float newS[6 * 16];
    float gh  [6 * GD];              // h @ Whh^T + b_hh (precomputed)
    float e   [36];
    float fc2b;
};

__global__ __launch_bounds__(256, 1) void k_scan(
    const float* __restrict__ h0,
    const float* __restrict__ W_hh0,
    const float* __restrict__ b_hh0,
    const float* __restrict__ W_ih,
    const float* __restrict__ W_hh,
    const float* __restrict__ b_ih,
    const float* __restrict__ b_hh,
    const float* __restrict__ Wa,
    const float* __restrict__ ba,
    const float* __restrict__ va,
    const float* __restrict__ fc1_w,
    const float* __restrict__ fc1_b,
    const float* __restrict__ fc2_w,
    const float* __restrict__ fc2_b,
    float* __restrict__ out)
{
    extern __shared__ char smem_raw[];
    Smem* s = reinterpret_cast<Smem*>(smem_raw);

    const int tid  = threadIdx.x;
    const int warp = tid >> 5;
    const int lane = tid & 31;
    const unsigned FULL = 0xffffffffu;

    // ---------------- load weights into shared (once) ----------------
    for (int idx = tid; idx < 5 * GD * HD; idx += 256) {
        int row = idx >> 4, hh = idx & 15;
        s->WihA[row * RP + hh] = W_ih[idx];
    }
    for (int idx = tid; idx < GD * HD; idx += 256) {
        int row = idx >> 4, hh = idx & 15;
        s->WhhA[row * RP + hh] = W_hh0[idx];
    }
    for (int idx = tid; idx < 5 * GD * HD; idx += 256) {
        int row = idx >> 4, hh = idx & 15;
        s->WhhA[(GD + row) * RP + hh] = W_hh[idx];
    }
    for (int idx = tid; idx < 6 * 16 * 64; idx += 256) s->Wa[idx] = Wa[idx];
    for (int idx = tid; idx < 6 * 64; idx += 256) { s->ba[idx] = ba[idx]; s->va[idx] = va[idx]; }
    for (int idx = tid; idx < 5 * GD; idx += 256) s->bihA[idx] = b_ih[idx];
    for (int idx = tid; idx < GD; idx += 256) s->bhhA[idx] = b_hh0[idx];
    for (int idx = tid; idx < 5 * GD; idx += 256) s->bhhA[GD + idx] = b_hh[idx];
    for (int idx = tid; idx < 32 * 16; idx += 256) {
        int row = idx >> 4, hh = idx & 15;
        s->fc1A[row * RP + hh] = fc1_w[idx];
    }
    if (tid < 32) { s->fc1b[tid] = fc1_b[tid]; s->fc2[tid] = fc2_w[tid]; }
    if (tid == 0) s->fc2b = fc2_b[0];
    for (int idx = tid; idx < 6 * 16; idx += 256) s->h[idx] = h0[idx];
    __syncthreads();

    // ---------------- initial gh from h0 (warps 0..5) ----------------
    if (warp < LN) {
        const int i = warp;
        float hv[16];
#pragma unroll
        for (int hh = 0; hh < 16; hh++) hv[hh] = s->h[i * 16 + hh];
        {
            const float* wb = &s->WhhA[(i * GD + lane) * RP];
            float a0 = s->bhhA[i * GD + lane];
#pragma unroll
            for (int hh = 0; hh < 16; hh++) a0 += hv[hh] * wb[hh];
            s->gh[i * GD + lane] = a0;
        }
        if (lane < 16) {
            const float* wb = &s->WhhA[(i * GD + 32 + lane) * RP];
            float a0 = s->bhhA[i * GD + 32 + lane];
#pragma unroll
            for (int hh = 0; hh < 16; hh++) a0 += hv[hh] * wb[hh];
            s->gh[i * GD + 32 + lane] = a0;
        }
    }
    if (warp == 0) {
        if (lane < 12) cp_async16(&s->gi0[lane * 4], &g_GI0[lane * 4]);
        asm volatile("cp.async.commit_group;\n");
    }
    __syncthreads();

    // persistent per-thread state for warp 0's GRU chain
    float inp[16];
    const int jlow = lane & 15;

    // energy pair worker
    auto energy = [&](int i, int l) {
        const int a0 = lane, a1 = lane + 32;
        float acc0 = s->ba[i * 64 + a0];
        float acc1 = s->ba[i * 64 + a1];
        const float* wa = &s->Wa[i * 16 * 64];
#pragma unroll
        for (int hh = 0; hh < 16; hh++) {
            float sv = s->newS[l * 16 + hh];
            acc0 += sv * wa[hh * 64 + a0];
            acc1 += sv * wa[hh * 64 + a1];
        }
        float v = tanhf_fast(acc0) * s->va[i * 64 + a0]
                + tanhf_fast(acc1) * s->va[i * 64 + a1];
#pragma unroll
        for (int off = 16; off; off >>= 1)
            v += __shfl_xor_sync(FULL, v, off);
        if (lane == 0) s->e[i * 6 + l] = v;
    };

    // one GRU layer l>=1 (warp 0, full warp). inp[] holds prev layer output
    // broadcast to all lanes; leaves this layer's output broadcast in inp[].
    auto gru_layer = [&](int l) {
        // primary row = lane (rows 0..15 => i_r, rows 16..31 => i_z)
        const float* wb = &s->WihA[((l - 1) * GD + lane) * RP];
        float4 w0 = *(const float4*)(wb);
        float4 w1 = *(const float4*)(wb + 4);
        float4 w2 = *(const float4*)(wb + 8);
        float4 w3 = *(const float4*)(wb + 12);
        float sA = w0.x*inp[0] + w0.y*inp[1] + w0.z*inp[2] + w0.w*inp[3]
                 + w1.x*inp[4] + w1.y*inp[5] + w1.z*inp[6] + w1.w*inp[7];
        float sB = w2.x*inp[8] + w2.y*inp[9] + w2.z*inp[10] + w2.w*inp[11]
                 + w3.x*inp[12] + w3.y*inp[13] + w3.z*inp[14] + w3.w*inp[15];
        float ap = sA + sB + s->bihA[(l - 1) * GD + lane] + s->gh[l * GD + lane];
        float gv = sigmoidf_fast(ap);               // lanes<16: r ; lanes>=16: z
        float zv = __shfl_sync(FULL, gv, 16 + jlow);
        float newh = 0.f;
        if (lane < 16) {
            const float* wn = &s->WihA[((l - 1) * GD + 32 + lane) * RP];
            float4 n0 = *(const float4*)(wn);
            float4 n1 = *(const float4*)(wn + 4);
            float4 n2 = *(const float4*)(wn + 8);
            float4 n3 = *(const float4*)(wn + 12);
            float tA = n0.x*inp[0] + n0.y*inp[1] + n0.z*inp[2] + n0.w*inp[3]
                     + n1.x*inp[4] + n1.y*inp[5] + n1.z*inp[6] + n1.w*inp[7];
            float tB = n2.x*inp[8] + n2.y*inp[9] + n2.z*inp[10] + n2.w*inp[11]
                     + n3.x*inp[12] + n3.y*inp[13] + n3.z*inp[14] + n3.w*inp[15];
            float an = tA + tB + s->bihA[(l - 1) * GD + 32 + lane]
                     + gv * s->gh[l * GD + 32 + lane];
            float n = tanhf_fast(an);
            newh = (1.f - zv) * n + zv * s->h[l * 16 + lane];
            s->newS[l * 16 + lane] = newh;
        }
#pragma unroll
        for (int hh = 0; hh < 16; hh++) inp[hh] = __shfl_sync(FULL, newh, hh);
    };

    // =========================== time loop ===========================
    for (int t = 0; t < T_STEPS; t++) {
        // -------- Phase A1: warp 0, layers 0..2 --------
        if (warp == 0) {
            if (lane < 12 && (t + 1) < T_STEPS)
                cp_async16(&s->gi0[((t + 1) & 1) * GD + lane * 4],
                           &g_GI0[(t + 1) * GD + lane * 4]);
            asm volatile("cp.async.commit_group;\n");
            asm volatile("cp.async.wait_group 1;\n");
            __syncwarp();

            const float* gi0 = &s->gi0[(t & 1) * GD];
            // layer 0: gi precomputed
            {
                float ap = gi0[lane] + s->gh[lane];
                float gv = sigmoidf_fast(ap);
                float zv = __shfl_sync(FULL, gv, 16 + jlow);
                float newh = 0.f;
                if (lane < 16) {
                    float an = gi0[32 + lane] + gv * s->gh[32 + lane];
                    float n = tanhf_fast(an);
                    newh = (1.f - zv) * n + zv * s->h[lane];
                    s->newS[lane] = newh;
                }
#pragma unroll
                for (int hh = 0; hh < 16; hh++) inp[hh] = __shfl_sync(FULL, newh, hh);
            }
            gru_layer(1);
            gru_layer(2);
        }
        __syncthreads();   // newS[0..2] visible

        // -------- Phase A2 (warp 0: layers 3..5) || E-early (warps 1..6) --------
        if (warp == 0) {
            gru_layer(3);
            gru_layer(4);
            gru_layer(5);   // leaves newS[5] broadcast in inp[]
        } else if (warp <= 6) {
            const int p = warp - 1;
            energy(c_PIE[p], c_PLE[p]);
        }
        __syncthreads();   // newS[3..5] visible

        // -------- Phase E-late (warps 1..7) || FC head (warp 0) --------
        if (warp == 0) {
            // out[t] = fc2 . (fc1 . newS[5] + b1) + b2   (h_next[5]==newS[5])
            const float* fb = &s->fc1A[lane * RP];
            float4 f0 = *(const float4*)(fb);
            float4 f1 = *(const float4*)(fb + 4);
            float4 f2 = *(const float4*)(fb + 8);
            float4 f3 = *(const float4*)(fb + 12);
            float aA = f0.x*inp[0] + f0.y*inp[1] + f0.z*inp[2] + f0.w*inp[3]
                     + f1.x*inp[4] + f1.y*inp[5] + f1.z*inp[6] + f1.w*inp[7];
            float aB = f2.x*inp[8] + f2.y*inp[9] + f2.z*inp[10] + f2.w*inp[11]
                     + f3.x*inp[12] + f3.y*inp[13] + f3.z*inp[14] + f3.w*inp[15];
            float acc = (aA + aB + s->fc1b[lane]) * s->fc2[lane];
#pragma unroll
            for (int off = 16; off; off >>= 1)
                acc += __shfl_xor_sync(FULL, acc, off);
            if (lane == 0) out[t] = acc + s->fc2b;
        } else {
            const int p0 = 2 * (warp - 1);
            energy(c_PIL[p0], c_PLL[p0]);
            energy(c_PIL[p0 + 1], c_PLL[p0 + 1]);
        }
        __syncthreads();   // all e visible

        // -------- Phase C: combine + gh precompute (warps 0..5) --------
        if (warp < LN) {
            const int i = warp;
            float hnew = 0.f;
            if (i < 5) {
                const int k = 6 - i;
                float ev[6], wv[6];
                float m = -1e30f;
                for (int q = 0; q < k; q++) {
                    ev[q] = s->e[i * 6 + (i + q)];
                    m = fmaxf(m, ev[q]);
                }
                float ssum = 0.f;
                for (int q = 0; q < k; q++) { wv[q] = __expf(ev[q] - m); ssum += wv[q]; }
                float inv = __fdividef(1.f, ssum);
                if (lane < 16) {
                    float acc = 0.f;
                    for (int q = 0; q < k; q++)
                        acc += wv[q] * s->newS[(i + q) * 16 + lane];
                    hnew = acc * inv;
                    s->h[i * 16 + lane] = hnew;
                }
            } else {
                if (lane < 16) {
                    hnew = s->newS[5 * 16 + lane];
                    s->h[5 * 16 + lane] = hnew;
                }
            }
            // broadcast new h row i, then gh[i] = h[i] @ Whh[i]^T + bhh[i]
            float hv[16];
#pragma unroll
            for (int hh = 0; hh < 16; hh++) hv[hh] = __shfl_sync(FULL, hnew, hh);
            {
                const float* wb = &s->WhhA[(i * GD + lane) * RP];
                float4 w0 = *(const float4*)(wb);
                float4 w1 = *(const float4*)(wb + 4);
                float4 w2 = *(const float4*)(wb + 8);
                float4 w3 = *(const float4*)(wb + 12);
                float aA = w0.x*hv[0] + w0.y*hv[1] + w0.z*hv[2] + w0.w*hv[3]
                         + w1.x*hv[4] + w1.y*hv[5] + w1.z*hv[6] + w1.w*hv[7];
                float aB = w2.x*hv[8] + w2.y*hv[9] + w2.z*hv[10] + w2.w*hv[11]
                         + w3.x*hv[12] + w3.y*hv[13] + w3.z*hv[14] + w3.w*hv[15];
                s->gh[i * GD + lane] = aA + aB + s->bhhA[i * GD + lane];
            }
            if (lane < 16) {
                const float* wb = &s->WhhA[(i * GD + 32 + lane) * RP];
                float4 w0 = *(const float4*)(wb);
                float4 w1 = *(const float4*)(wb + 4);
                float4 w2 = *(const float4*)(wb + 8);
                float4 w3 = *(const float4*)(wb + 12);
                float aA = w0.x*hv[0] + w0.y*hv[1] + w0.z*hv[2] + w0.w*hv[3]
                         + w1.x*hv[4] + w1.y*hv[5] + w1.z*hv[6] + w1.w*hv[7];
                float aB = w2.x*hv[8] + w2.y*hv[9] + w2.z*hv[10] + w2.w*hv[11]
                         + w3.x*hv[12] + w3.y*hv[13] + w3.z*hv[14] + w3.w*hv[15];
                s->gh[i * GD + 32 + lane] = aA + aB + s->bhhA[i * GD + 32 + lane];
            }
        }
        __syncthreads();   // h, gh ready for next step
    }
}

// ---------------------------------------------------------------------------
extern "C" void kernel_launch(void* const* d_in, const int* in_sizes, int n_in,
                              void* d_out, int out_size)
{
    const float* batch  = (const float*)d_in[0];
    const float* h0     = (const float*)d_in[1];
    const float* W_ih0  = (const float*)d_in[2];
    const float* W_hh0  = (const float*)d_in[3];
    const float* b_ih0  = (const float*)d_in[4];
    const float* b_hh0  = (const float*)d_in[5];
    const float* W_ih   = (const float*)d_in[6];
    const float* W_hh   = (const float*)d_in[7];
    const float* b_ih   = (const float*)d_in[8];
    const float* b_hh   = (const float*)d_in[9];
    const float* Wa     = (const float*)d_in[10];
    const float* ba     = (const float*)d_in[11];
    const float* va     = (const float*)d_in[12];
    const float* fc1_w  = (const float*)d_in[13];
    const float* fc1_b  = (const float*)d_in[14];
    const float* fc2_w  = (const float*)d_in[15];
    const float* fc2_b  = (const float*)d_in[16];
    float* out = (float*)d_out;

    cudaFuncSetAttribute(k_scan, cudaFuncAttributeMaxDynamicSharedMemorySize,
                         (int)sizeof(Smem));

    k_gi0<<<T_STEPS / 32, 256>>>(batch, W_ih0, b_ih0);
    k_scan<<<1, 256, sizeof(Smem)>>>(h0, W_hh0, b_hh0, W_ih, W_hh, b_ih, b_hh,
                                     Wa, ba, va, fc1_w, fc1_b, fc2_w, fc2_b, out);
}

// round 5
// speedup vs baseline: 1.2927x; 1.1834x over previous
#include <cuda_runtime.h>
#include <cuda_bf16.h>
#include <cstdint>

#define T_STEPS 16384
#define F_IN    2048
#define HD      16
#define GD      48
#define LN      6
#define AD      64
#define WROW    36   // per-lane packed weight slot: 16 prim + 16 n + 4 pad

typedef unsigned long long ull;

// scratch for precomputed layer-0 input projection (gi0 = x @ W_ih0^T + b_ih0)
__device__ float g_GI0[T_STEPS * GD];

// Early energy pairs (l <= 3): overlap with GRU layers 4..5. warps 1..5, 2 each.
__constant__ int c_PIE[10] = {0,0, 1,0, 1,2, 0,1, 2,3};
__constant__ int c_PLE[10] = {0,1, 1,2, 2,2, 3,3, 3,3};
// Late energy pairs (l in {4,5}). warps 1..5, 2 each.
__constant__ int c_PIL[10] = {0,0, 1,1, 2,2, 3,3, 4,4};
__constant__ int c_PLL[10] = {4,5, 4,5, 4,5, 4,5, 4,5};

__device__ __forceinline__ float sigmoidf_fast(float x) {
    return __fdividef(1.f, 1.f + __expf(-x));
}
__device__ __forceinline__ float tanhf_fast(float x) {
    float ax = fabsf(x);
    float e  = __expf(-2.f * ax);
    float r  = __fdividef(1.f - e, 1.f + e);
    return copysignf(r, x);
}

__device__ __forceinline__ ull ffma2(ull a, ull b, ull c) {
    ull d; asm("fma.rn.f32x2 %0, %1, %2, %3;" : "=l"(d) : "l"(a), "l"(b), "l"(c));
    return d;
}
__device__ __forceinline__ ull fadd2(ull a, ull b) {
    ull d; asm("add.rn.f32x2 %0, %1, %2;" : "=l"(d) : "l"(a), "l"(b));
    return d;
}
__device__ __forceinline__ ull pk(float lo, float hi) {
    ull d; asm("mov.b64 %0, {%1, %2};" : "=l"(d) : "f"(lo), "f"(hi));
    return d;
}
__device__ __forceinline__ float hsum(ull v) {
    float lo, hi; asm("mov.b64 {%0, %1}, %2;" : "=f"(lo), "=f"(hi) : "l"(v));
    return lo + hi;
}

__device__ __forceinline__ void cp_async16(void* smem_dst, const void* gsrc) {
    unsigned sa = (unsigned)__cvta_generic_to_shared(smem_dst);
    asm volatile("cp.async.ca.shared.global [%0], [%1], 16;\n" :: "r"(sa), "l"(gsrc));
}

// ---------------------------------------------------------------------------
// Kernel 1: GI0[t][g] = b_ih0[g] + sum_f batch[t][f] * W_ih0[g][f]
// ---------------------------------------------------------------------------
__global__ __launch_bounds__(256) void k_gi0(
    const float* __restrict__ batch,
    const float* __restrict__ Wih0,
    const float* __restrict__ bih0)
{
    __shared__ float Bs[32 * 65];
    __shared__ float Ws[48 * 64];
    const int t0  = blockIdx.x * 32;
    const int tid = threadIdx.x;
    const int tl  = tid & 31;
    const int gg  = tid >> 5;
    const int g0  = gg * 6;

    float acc[6];
#pragma unroll
    for (int j = 0; j < 6; j++) acc[j] = 0.f;

    for (int k0 = 0; k0 < F_IN; k0 += 64) {
        __syncthreads();
#pragma unroll
        for (int i = 0; i < 8; i++) {
            int idx = tid + i * 256;
            int r = idx >> 6, c = idx & 63;
            Bs[r * 65 + c] = batch[(t0 + r) * F_IN + k0 + c];
        }
#pragma unroll
        for (int i = 0; i < 12; i++) {
            int idx = tid + i * 256;
            int r = idx >> 6, c = idx & 63;
            Ws[r * 64 + c] = Wih0[r * F_IN + k0 + c];
        }
        __syncthreads();
#pragma unroll 4
        for (int kk = 0; kk < 64; kk++) {
            float b = Bs[tl * 65 + kk];
#pragma unroll
            for (int j = 0; j < 6; j++) acc[j] += b * Ws[(g0 + j) * 64 + kk];
        }
    }
#pragma unroll
    for (int j = 0; j < 6; j++)
        g_GI0[(t0 + tl) * GD + g0 + j] = acc[j] + bih0[g0 + j];
}

// ---------------------------------------------------------------------------
// Kernel 2: persistent single-block sequential scan.
// ---------------------------------------------------------------------------
struct Smem {
    float gi0 [2 * GD];          // 16B aligned, cp.async target
    float Wih2[5 * 32 * WROW];   // layers1..5 per-lane [prim16|n16|pad4]
    float Whh2[6 * 32 * WROW];
    float Wac [6 * 64 * 18];     // attention weights column-major, col slot 18
    float fc1r[32 * 20];
    float ba  [6 * 64];
    float va  [6 * 64];
    float bihPr[5 * 32];
    float bihN [5 * 16];
    float bhhPr[6 * 32];
    float bhhN [6 * 16];
    float fc1b[32];
    float fc2 [32];
    float h   [6 * 16];
    float newS[6 * 16];
    float ghP [6 * 32];          // per-step: prim gh (incl bhh)
    float ghN [6 * 16];          // per-step: n gh (incl bhh_n)
    float e   [36];
    float fc2b;
    float pad[3];
};

__global__ __launch_bounds__(256, 1) void k_scan(
    const float* __restrict__ h0,
    const float* __restrict__ W_hh0,
    const float* __restrict__ b_hh0,
    const float* __restrict__ W_ih,
    const float* __restrict__ W_hh,
    const float* __restrict__ b_ih,
    const float* __restrict__ b_hh,
    const float* __restrict__ Wa,
    const float* __restrict__ ba,
    const float* __restrict__ va,
    const float* __restrict__ fc1_w,
    const float* __restrict__ fc1_b,
    const float* __restrict__ fc2_w,
    const float* __restrict__ fc2_b,
    float* __restrict__ out)
{
    extern __shared__ char smem_raw[];
    Smem* s = reinterpret_cast<Smem*>(smem_raw);

    const int tid  = threadIdx.x;
    const int warp = tid >> 5;
    const int lane = tid & 31;
    const int jlow = lane & 15;
    const unsigned FULL = 0xffffffffu;

    // ---------------- build packed layouts in shared (once) ----------------
    for (int idx = tid; idx < 5 * 32 * 16; idx += 256) {
        int hh = idx & 15, r = idx >> 4;      // r = l'*32 + lane
        int l = r >> 5, ln = r & 31;
        s->Wih2[r * WROW + hh]      = W_ih[l * 768 + ln * 16 + hh];
        s->Wih2[r * WROW + 16 + hh] = (ln < 16) ? W_ih[l * 768 + (32 + ln) * 16 + hh] : 0.f;
    }
    for (int idx = tid; idx < 6 * 32 * 16; idx += 256) {
        int hh = idx & 15, r = idx >> 4;
        int i = r >> 5, ln = r & 31;
        float prim, nw;
        if (i == 0) {
            prim = W_hh0[ln * 16 + hh];
            nw   = (ln < 16) ? W_hh0[(32 + ln) * 16 + hh] : 0.f;
        } else {
            prim = W_hh[(i - 1) * 768 + ln * 16 + hh];
            nw   = (ln < 16) ? W_hh[(i - 1) * 768 + (32 + ln) * 16 + hh] : 0.f;
        }
        s->Whh2[r * WROW + hh]      = prim;
        s->Whh2[r * WROW + 16 + hh] = nw;
    }
    for (int idx = tid; idx < 6 * 16 * 64; idx += 256) {
        int i = idx >> 10;
        int rem = idx & 1023;
        int hh = rem >> 6, col = rem & 63;
        s->Wac[(i * 64 + col) * 18 + hh] = Wa[idx];
    }
    for (int idx = tid; idx < 32 * 16; idx += 256) {
        int row = idx >> 4, hh = idx & 15;
        s->fc1r[row * 20 + hh] = fc1_w[idx];
    }
    for (int idx = tid; idx < 6 * 64; idx += 256) { s->ba[idx] = ba[idx]; s->va[idx] = va[idx]; }
    for (int idx = tid; idx < 5 * 32; idx += 256) {
        int l = idx >> 5, ln = idx & 31;
        s->bihPr[idx] = b_ih[l * 48 + ln];
    }
    for (int idx = tid; idx < 5 * 16; idx += 256) {
        int l = idx >> 4, j = idx & 15;
        s->bihN[idx] = b_ih[l * 48 + 32 + j];
    }
    for (int idx = tid; idx < 6 * 32; idx += 256) {
        int i = idx >> 5, ln = idx & 31;
        s->bhhPr[idx] = (i == 0) ? b_hh0[ln] : b_hh[(i - 1) * 48 + ln];
    }
    for (int idx = tid; idx < 6 * 16; idx += 256) {
        int i = idx >> 4, j = idx & 15;
        s->bhhN[idx] = (i == 0) ? b_hh0[32 + j] : b_hh[(i - 1) * 48 + 32 + j];
    }
    if (tid < 32) { s->fc1b[tid] = fc1_b[tid]; s->fc2[tid] = fc2_w[tid]; }
    if (tid == 0) s->fc2b = fc2_b[0];
    for (int idx = tid; idx < 6 * 16; idx += 256) s->h[idx] = h0[idx];
    __syncthreads();

    // gh precompute for layer i from current s->h[i]
    auto gh_update = [&](int i) {
        const float* wl = &s->Whh2[(i * 32 + lane) * WROW];
        const ulonglong2* wpv = (const ulonglong2*)wl;
        const ulonglong2* wnv = (const ulonglong2*)(wl + 16);
        const ull* ip = (const ull*)&s->h[i * 16];
        ull p0 = pk(s->bhhPr[i * 32 + lane], 0.f), p1 = 0ull;
        ull q0 = pk(s->bhhN[i * 16 + jlow], 0.f), q1 = 0ull;
#pragma unroll
        for (int k = 0; k < 4; k++) {
            ulonglong2 wp = wpv[k], wn = wnv[k];
            ull x0 = ip[2 * k], x1 = ip[2 * k + 1];
            p0 = ffma2(wp.x, x0, p0); p1 = ffma2(wp.y, x1, p1);
            q0 = ffma2(wn.x, x0, q0); q1 = ffma2(wn.y, x1, q1);
        }
        s->ghP[i * 32 + lane] = hsum(fadd2(p0, p1));
        if (lane < 16) s->ghN[i * 16 + lane] = hsum(fadd2(q0, q1));
    };

    // ---------------- initial gh from h0 ----------------
    if (warp < LN) gh_update(warp);
    if (warp == 0) {
        if (lane < 12) cp_async16(&s->gi0[lane * 4], &g_GI0[lane * 4]);
        asm volatile("cp.async.commit_group;\n");
    }
    __syncthreads();

    // one GRU layer l>=1 (warp 0, full warp, uniform stream)
    auto gru_layer = [&](int l) {
        const float* wl = &s->Wih2[((l - 1) * 32 + lane) * WROW];
        const ulonglong2* wpv = (const ulonglong2*)wl;
        const ulonglong2* wnv = (const ulonglong2*)(wl + 16);
        const ull* ip = (const ull*)&s->newS[(l - 1) * 16];
        float ghp = s->ghP[l * 32 + lane];
        float ghn = s->ghN[l * 16 + jlow];
        float hp  = s->h[l * 16 + jlow];
        ull p0 = pk(s->bihPr[(l - 1) * 32 + lane], 0.f), p1 = 0ull;
        ull q0 = pk(s->bihN[(l - 1) * 16 + jlow], 0.f), q1 = 0ull;
#pragma unroll
        for (int k = 0; k < 4; k++) {
            ulonglong2 wp = wpv[k], wn = wnv[k];
            ull x0 = ip[2 * k], x1 = ip[2 * k + 1];
            p0 = ffma2(wp.x, x0, p0); p1 = ffma2(wp.y, x1, p1);
            q0 = ffma2(wn.x, x0, q0); q1 = ffma2(wn.y, x1, q1);
        }
        float ap = hsum(fadd2(p0, p1)) + ghp;
        float gv = sigmoidf_fast(ap);
        float zv = __shfl_sync(FULL, gv, 16 + jlow);
        float an = hsum(fadd2(q0, q1)) + gv * ghn;
        float n  = tanhf_fast(an);
        float newh = n + zv * (hp - n);
        if (lane < 16) s->newS[l * 16 + lane] = newh;
        __syncwarp();
    };

    // two energy pairs computed together: independent FMA/tanh/reduce chains
    // interleave, so the two 5-level SHFL reductions overlap.
    auto energy2 = [&](int iA, int lA, int iB, int lB) {
        const ull* ipA = (const ull*)&s->newS[lA * 16];
        const ull* ipB = (const ull*)&s->newS[lB * 16];
        const int c0 = lane, c1 = lane + 32;
        const ull* wA0 = (const ull*)&s->Wac[(iA * 64 + c0) * 18];
        const ull* wA1 = (const ull*)&s->Wac[(iA * 64 + c1) * 18];
        const ull* wB0 = (const ull*)&s->Wac[(iB * 64 + c0) * 18];
        const ull* wB1 = (const ull*)&s->Wac[(iB * 64 + c1) * 18];
        ull a0 = 0ull, a1 = 0ull, a2 = 0ull, a3 = 0ull;
        ull b0 = 0ull, b1 = 0ull, b2 = 0ull, b3 = 0ull;
#pragma unroll
        for (int k = 0; k < 4; k++) {
            ull xA0 = ipA[2 * k], xA1 = ipA[2 * k + 1];
            ull xB0 = ipB[2 * k], xB1 = ipB[2 * k + 1];
            a0 = ffma2(wA0[2 * k], xA0, a0); a1 = ffma2(wA0[2 * k + 1], xA1, a1);
            a2 = ffma2(wA1[2 * k], xA0, a2); a3 = ffma2(wA1[2 * k + 1], xA1, a3);
            b0 = ffma2(wB0[2 * k], xB0, b0); b1 = ffma2(wB0[2 * k + 1], xB1, b1);
            b2 = ffma2(wB1[2 * k], xB0, b2); b3 = ffma2(wB1[2 * k + 1], xB1, b3);
        }
        float eA0 = hsum(fadd2(a0, a1)) + s->ba[iA * 64 + c0];
        float eA1 = hsum(fadd2(a2, a3)) + s->ba[iA * 64 + c1];
        float eB0 = hsum(fadd2(b0, b1)) + s->ba[iB * 64 + c0];
        float eB1 = hsum(fadd2(b2, b3)) + s->ba[iB * 64 + c1];
        float vA = tanhf_fast(eA0) * s->va[iA * 64 + c0]
                 + tanhf_fast(eA1) * s->va[iA * 64 + c1];
        float vB = tanhf_fast(eB0) * s->va[iB * 64 + c0]
                 + tanhf_fast(eB1) * s->va[iB * 64 + c1];
#pragma unroll
        for (int off = 16; off; off >>= 1) {
            vA += __shfl_xor_sync(FULL, vA, off);
            vB += __shfl_xor_sync(FULL, vB, off);
        }
        if (lane == 0) { s->e[iA * 6 + lA] = vA; s->e[iB * 6 + lB] = vB; }
    };

    // =========================== time loop ===========================
    for (int t = 0; t < T_STEPS; t++) {
        // -------- Phase A1: warp 0, layers 0..3 --------
        if (warp == 0) {
            if (lane < 12 && (t + 1) < T_STEPS)
                cp_async16(&s->gi0[((t + 1) & 1) * GD + lane * 4],
                           &g_GI0[(t + 1) * GD + lane * 4]);
            asm volatile("cp.async.commit_group;\n");
            asm volatile("cp.async.wait_group 1;\n");
            __syncwarp();

            const float* g = &s->gi0[(t & 1) * GD];
            // layer 0 (gi precomputed incl b_ih0)
            {
                float ap = g[lane] + s->ghP[lane];
                float gv = sigmoidf_fast(ap);
                float zv = __shfl_sync(FULL, gv, 16 + jlow);
                float an = g[32 + jlow] + gv * s->ghN[jlow];
                float n  = tanhf_fast(an);
                float hp = s->h[jlow];
                float newh = n + zv * (hp - n);
                if (lane < 16) s->newS[lane] = newh;
                __syncwarp();
            }
            gru_layer(1);
            gru_layer(2);
            gru_layer(3);
        }
        __syncthreads();   // newS[0..3] visible

        // -------- Phase A2 (warp0: layers 4..5) || E-early (warps 1..5) --------
        if (warp == 0) {
            gru_layer(4);
            gru_layer(5);
        } else if (warp <= 5) {
            const int p = (warp - 1) * 2;
            energy2(c_PIE[p], c_PLE[p], c_PIE[p + 1], c_PLE[p + 1]);
        }
        __syncthreads();   // newS[4..5] visible

        // -------- Phase E-late (warps 1..5) || FC head (warp 0) --------
        if (warp == 0) {
            const ull* ip = (const ull*)&s->newS[5 * 16];
            const ull* fw = (const ull*)&s->fc1r[lane * 20];
            ull a0 = 0ull, a1 = 0ull;
#pragma unroll
            for (int k = 0; k < 4; k++) {
                a0 = ffma2(fw[2 * k], ip[2 * k], a0);
                a1 = ffma2(fw[2 * k + 1], ip[2 * k + 1], a1);
            }
            float acc = (hsum(fadd2(a0, a1)) + s->fc1b[lane]) * s->fc2[lane];
#pragma unroll
            for (int off = 16; off; off >>= 1)
                acc += __shfl_xor_sync(FULL, acc, off);
            if (lane == 0) out[t] = acc + s->fc2b;
        } else if (warp <= 5) {
            const int p = (warp - 1) * 2;
            energy2(c_PIL[p], c_PLL[p], c_PIL[p + 1], c_PLL[p + 1]);
        }
        __syncthreads();   // all e visible

        // -------- Phase C: combine + gh precompute (warps 0..5) --------
        if (warp < LN) {
            const int i = warp;
            if (i < 5) {
                const int k = 6 - i;
                float ev[6], wv[6];
                float m = -1e30f;
                for (int q = 0; q < k; q++) {
                    ev[q] = s->e[i * 6 + (i + q)];
                    m = fmaxf(m, ev[q]);
                }
                float ssum = 0.f;
                for (int q = 0; q < k; q++) { wv[q] = __expf(ev[q] - m); ssum += wv[q]; }
                float inv = __fdividef(1.f, ssum);
                if (lane < 16) {
                    float acc = 0.f;
                    for (int q = 0; q < k; q++)
                        acc += wv[q] * s->newS[(i + q) * 16 + lane];
                    s->h[i * 16 + lane] = acc * inv;
                }
            } else {
                if (lane < 16) s->h[5 * 16 + lane] = s->newS[5 * 16 + lane];
            }
            __syncwarp();
            gh_update(i);
        }
        __syncthreads();   // h, ghP, ghN ready for next step
    }
}

// ---------------------------------------------------------------------------
extern "C" void kernel_launch(void* const* d_in, const int* in_sizes, int n_in,
                              void* d_out, int out_size)
{
    const float* batch  = (const float*)d_in[0];
    const float* h0     = (const float*)d_in[1];
    const float* W_ih0  = (const float*)d_in[2];
    const float* W_hh0  = (const float*)d_in[3];
    const float* b_ih0  = (const float*)d_in[4];
    const float* b_hh0  = (const float*)d_in[5];
    const float* W_ih   = (const float*)d_in[6];
    const float* W_hh   = (const float*)d_in[7];
    const float* b_ih   = (const float*)d_in[8];
    const float* b_hh   = (const float*)d_in[9];
    const float* Wa     = (const float*)d_in[10];
    const float* ba     = (const float*)d_in[11];
    const float* va     = (const float*)d_in[12];
    const float* fc1_w  = (const float*)d_in[13];
    const float* fc1_b  = (const float*)d_in[14];
    const float* fc2_w  = (const float*)d_in[15];
    const float* fc2_b  = (const float*)d_in[16];
    float* out = (float*)d_out;

    cudaFuncSetAttribute(k_scan, cudaFuncAttributeMaxDynamicSharedMemorySize,
                         (int)sizeof(Smem));

    k_gi0<<<T_STEPS / 32, 256>>>(batch, W_ih0, b_ih0);
    k_scan<<<1, 256, sizeof(Smem)>>>(h0, W_hh0, b_hh0, W_ih, W_hh, b_ih, b_hh,
                                     Wa, ba, va, fc1_w, fc1_b, fc2_w, fc2_b, out);
}

// round 6
// speedup vs baseline: 1.6931x; 1.3097x over previous
#include <cuda_runtime.h>
#include <cuda_bf16.h>
#include <cstdint>

#define T_STEPS 16384
#define F_IN    2048
#define HD      16
#define GD      48
#define LN      6
#define AD      64
#define WROW    36   // per-lane packed weight slot: 16 prim + 16 n + 4 pad

typedef unsigned long long ull;

// scratch for precomputed layer-0 input projection (gi0 = x @ W_ih0^T + b_ih0)
__device__ float g_GI0[T_STEPS * GD];

// Early energy pairs (l <= 3): overlap with GRU layers 4..5. warps 1..5, 2 each.
__constant__ int c_PIE[10] = {0,0, 1,0, 1,2, 0,1, 2,3};
__constant__ int c_PLE[10] = {0,1, 1,2, 2,2, 3,3, 3,3};

__device__ __forceinline__ float tanh_mufu(float x) {
    float r; asm("tanh.approx.f32 %0, %1;" : "=f"(r) : "f"(x));
    return r;
}
__device__ __forceinline__ float sigmoid_mufu(float x) {
    return fmaf(tanh_mufu(0.5f * x), 0.5f, 0.5f);
}

__device__ __forceinline__ ull ffma2(ull a, ull b, ull c) {
    ull d; asm("fma.rn.f32x2 %0, %1, %2, %3;" : "=l"(d) : "l"(a), "l"(b), "l"(c));
    return d;
}
__device__ __forceinline__ ull fadd2(ull a, ull b) {
    ull d; asm("add.rn.f32x2 %0, %1, %2;" : "=l"(d) : "l"(a), "l"(b));
    return d;
}
__device__ __forceinline__ ull pk(float lo, float hi) {
    ull d; asm("mov.b64 %0, {%1, %2};" : "=l"(d) : "f"(lo), "f"(hi));
    return d;
}
__device__ __forceinline__ float hsum(ull v) {
    float lo, hi; asm("mov.b64 {%0, %1}, %2;" : "=f"(lo), "=f"(hi) : "l"(v));
    return lo + hi;
}

__device__ __forceinline__ void cp_async16(void* smem_dst, const void* gsrc) {
    unsigned sa = (unsigned)__cvta_generic_to_shared(smem_dst);
    asm volatile("cp.async.ca.shared.global [%0], [%1], 16;\n" :: "r"(sa), "l"(gsrc));
}

// ---------------------------------------------------------------------------
// Kernel 1: GI0[t][g] = b_ih0[g] + sum_f batch[t][f] * W_ih0[g][f]
// ---------------------------------------------------------------------------
__global__ __launch_bounds__(256) void k_gi0(
    const float* __restrict__ batch,
    const float* __restrict__ Wih0,
    const float* __restrict__ bih0)
{
    __shared__ float Bs[32 * 65];
    __shared__ float Ws[48 * 64];
    const int t0  = blockIdx.x * 32;
    const int tid = threadIdx.x;
    const int tl  = tid & 31;
    const int gg  = tid >> 5;
    const int g0  = gg * 6;

    float acc[6];
#pragma unroll
    for (int j = 0; j < 6; j++) acc[j] = 0.f;

    for (int k0 = 0; k0 < F_IN; k0 += 64) {
        __syncthreads();
#pragma unroll
        for (int i = 0; i < 8; i++) {
            int idx = tid + i * 256;
            int r = idx >> 6, c = idx & 63;
            Bs[r * 65 + c] = batch[(t0 + r) * F_IN + k0 + c];
        }
#pragma unroll
        for (int i = 0; i < 12; i++) {
            int idx = tid + i * 256;
            int r = idx >> 6, c = idx & 63;
            Ws[r * 64 + c] = Wih0[r * F_IN + k0 + c];
        }
        __syncthreads();
#pragma unroll 4
        for (int kk = 0; kk < 64; kk++) {
            float b = Bs[tl * 65 + kk];
#pragma unroll
            for (int j = 0; j < 6; j++) acc[j] += b * Ws[(g0 + j) * 64 + kk];
        }
    }
#pragma unroll
    for (int j = 0; j < 6; j++)
        g_GI0[(t0 + tl) * GD + g0 + j] = acc[j] + bih0[g0 + j];
}

// ---------------------------------------------------------------------------
// Kernel 2: persistent single-block sequential scan.
// ---------------------------------------------------------------------------
struct Smem {
    float gi0 [2 * GD];          // 16B aligned, cp.async target
    float Wih2[5 * 32 * WROW];   // layers1..5 per-lane [prim16|n16|pad4]
    float Whh2[6 * 32 * WROW];
    float Wac [6 * 64 * 18];     // attention weights column-major, col slot 18
    float fc1r[32 * 20];
    float ba  [6 * 64];
    float va  [6 * 64];
    float bihPr[5 * 32];
    float bihN [5 * 16];
    float bhhPr[6 * 32];
    float bhhN [6 * 16];
    float fc1b[32];
    float fc2 [32];
    float h   [6 * 16];
    float newS[6 * 16];
    float ghP [6 * 32];          // per-step: prim gh (incl bhh)
    float ghN [6 * 16];          // per-step: n gh (incl bhh_n)
    float e   [36];              // only early (l<=3) energies pass through here
    float fc2b;
    float pad[3];
};

__global__ __launch_bounds__(256, 1) void k_scan(
    const float* __restrict__ h0,
    const float* __restrict__ W_hh0,
    const float* __restrict__ b_hh0,
    const float* __restrict__ W_ih,
    const float* __restrict__ W_hh,
    const float* __restrict__ b_ih,
    const float* __restrict__ b_hh,
    const float* __restrict__ Wa,
    const float* __restrict__ ba,
    const float* __restrict__ va,
    const float* __restrict__ fc1_w,
    const float* __restrict__ fc1_b,
    const float* __restrict__ fc2_w,
    const float* __restrict__ fc2_b,
    float* __restrict__ out)
{
    extern __shared__ char smem_raw[];
    Smem* s = reinterpret_cast<Smem*>(smem_raw);

    const int tid  = threadIdx.x;
    const int warp = tid >> 5;
    const int lane = tid & 31;
    const int jlow = lane & 15;
    const unsigned FULL = 0xffffffffu;

    // ---------------- build packed layouts in shared (once) ----------------
    for (int idx = tid; idx < 5 * 32 * 16; idx += 256) {
        int hh = idx & 15, r = idx >> 4;      // r = l'*32 + lane
        int l = r >> 5, ln = r & 31;
        s->Wih2[r * WROW + hh]      = W_ih[l * 768 + ln * 16 + hh];
        s->Wih2[r * WROW + 16 + hh] = (ln < 16) ? W_ih[l * 768 + (32 + ln) * 16 + hh] : 0.f;
    }
    for (int idx = tid; idx < 6 * 32 * 16; idx += 256) {
        int hh = idx & 15, r = idx >> 4;
        int i = r >> 5, ln = r & 31;
        float prim, nw;
        if (i == 0) {
            prim = W_hh0[ln * 16 + hh];
            nw   = (ln < 16) ? W_hh0[(32 + ln) * 16 + hh] : 0.f;
        } else {
            prim = W_hh[(i - 1) * 768 + ln * 16 + hh];
            nw   = (ln < 16) ? W_hh[(i - 1) * 768 + (32 + ln) * 16 + hh] : 0.f;
        }
        s->Whh2[r * WROW + hh]      = prim;
        s->Whh2[r * WROW + 16 + hh] = nw;
    }
    for (int idx = tid; idx < 6 * 16 * 64; idx += 256) {
        int i = idx >> 10;
        int rem = idx & 1023;
        int hh = rem >> 6, col = rem & 63;
        s->Wac[(i * 64 + col) * 18 + hh] = Wa[idx];
    }
    for (int idx = tid; idx < 32 * 16; idx += 256) {
        int row = idx >> 4, hh = idx & 15;
        s->fc1r[row * 20 + hh] = fc1_w[idx];
    }
    for (int idx = tid; idx < 6 * 64; idx += 256) { s->ba[idx] = ba[idx]; s->va[idx] = va[idx]; }
    for (int idx = tid; idx < 5 * 32; idx += 256) {
        int l = idx >> 5, ln = idx & 31;
        s->bihPr[idx] = b_ih[l * 48 + ln];
    }
    for (int idx = tid; idx < 5 * 16; idx += 256) {
        int l = idx >> 4, j = idx & 15;
        s->bihN[idx] = b_ih[l * 48 + 32 + j];
    }
    for (int idx = tid; idx < 6 * 32; idx += 256) {
        int i = idx >> 5, ln = idx & 31;
        s->bhhPr[idx] = (i == 0) ? b_hh0[ln] : b_hh[(i - 1) * 48 + ln];
    }
    for (int idx = tid; idx < 6 * 16; idx += 256) {
        int i = idx >> 4, j = idx & 15;
        s->bhhN[idx] = (i == 0) ? b_hh0[32 + j] : b_hh[(i - 1) * 48 + 32 + j];
    }
    if (tid < 32) { s->fc1b[tid] = fc1_b[tid]; s->fc2[tid] = fc2_w[tid]; }
    if (tid == 0) s->fc2b = fc2_b[0];
    for (int idx = tid; idx < 6 * 16; idx += 256) s->h[idx] = h0[idx];
    __syncthreads();

    // gh precompute for layer i from current s->h[i]
    auto gh_update = [&](int i) {
        const float* wl = &s->Whh2[(i * 32 + lane) * WROW];
        const ulonglong2* wpv = (const ulonglong2*)wl;
        const ulonglong2* wnv = (const ulonglong2*)(wl + 16);
        const ull* ip = (const ull*)&s->h[i * 16];
        ull p0 = pk(s->bhhPr[i * 32 + lane], 0.f), p1 = 0ull;
        ull q0 = pk(s->bhhN[i * 16 + jlow], 0.f), q1 = 0ull;
#pragma unroll
        for (int k = 0; k < 4; k++) {
            ulonglong2 wp = wpv[k], wn = wnv[k];
            ull x0 = ip[2 * k], x1 = ip[2 * k + 1];
            p0 = ffma2(wp.x, x0, p0); p1 = ffma2(wp.y, x1, p1);
            q0 = ffma2(wn.x, x0, q0); q1 = ffma2(wn.y, x1, q1);
        }
        s->ghP[i * 32 + lane] = hsum(fadd2(p0, p1));
        if (lane < 16) s->ghN[i * 16 + lane] = hsum(fadd2(q0, q1));
    };

    // ---------------- initial gh from h0 ----------------
    if (warp < LN) gh_update(warp);
    if (warp == 0) {
        if (lane < 12) cp_async16(&s->gi0[lane * 4], &g_GI0[lane * 4]);
        asm volatile("cp.async.commit_group;\n");
    }
    __syncthreads();

    // one GRU layer l>=1 (warp 0, full warp, uniform stream)
    auto gru_layer = [&](int l) {
        const float* wl = &s->Wih2[((l - 1) * 32 + lane) * WROW];
        const ulonglong2* wpv = (const ulonglong2*)wl;
        const ulonglong2* wnv = (const ulonglong2*)(wl + 16);
        const ull* ip = (const ull*)&s->newS[(l - 1) * 16];
        float ghp = s->ghP[l * 32 + lane];
        float ghn = s->ghN[l * 16 + jlow];
        float hp  = s->h[l * 16 + jlow];
        ull p0 = pk(s->bihPr[(l - 1) * 32 + lane], 0.f), p1 = 0ull;
        ull q0 = pk(s->bihN[(l - 1) * 16 + jlow], 0.f), q1 = 0ull;
#pragma unroll
        for (int k = 0; k < 4; k++) {
            ulonglong2 wp = wpv[k], wn = wnv[k];
            ull x0 = ip[2 * k], x1 = ip[2 * k + 1];
            p0 = ffma2(wp.x, x0, p0); p1 = ffma2(wp.y, x1, p1);
            q0 = ffma2(wn.x, x0, q0); q1 = ffma2(wn.y, x1, q1);
        }
        float ap = hsum(fadd2(p0, p1)) + ghp;
        float gv = sigmoid_mufu(ap);                 // lanes<16: r ; lanes>=16: z
        float zv = __shfl_sync(FULL, gv, 16 + jlow);
        float an = hsum(fadd2(q0, q1)) + gv * ghn;   // uses local r (lanes<16)
        float n  = tanh_mufu(an);
        float newh = n + zv * (hp - n);
        if (lane < 16) s->newS[l * 16 + lane] = newh;
        __syncwarp();
    };

    // two energy pairs computed together (for the early/overlap phase)
    auto energy2 = [&](int iA, int lA, int iB, int lB) {
        const ull* ipA = (const ull*)&s->newS[lA * 16];
        const ull* ipB = (const ull*)&s->newS[lB * 16];
        const int c0 = lane, c1 = lane + 32;
        const ull* wA0 = (const ull*)&s->Wac[(iA * 64 + c0) * 18];
        const ull* wA1 = (const ull*)&s->Wac[(iA * 64 + c1) * 18];
        const ull* wB0 = (const ull*)&s->Wac[(iB * 64 + c0) * 18];
        const ull* wB1 = (const ull*)&s->Wac[(iB * 64 + c1) * 18];
        ull a0 = 0ull, a1 = 0ull, a2 = 0ull, a3 = 0ull;
        ull b0 = 0ull, b1 = 0ull, b2 = 0ull, b3 = 0ull;
#pragma unroll
        for (int k = 0; k < 4; k++) {
            ull xA0 = ipA[2 * k], xA1 = ipA[2 * k + 1];
            ull xB0 = ipB[2 * k], xB1 = ipB[2 * k + 1];
            a0 = ffma2(wA0[2 * k], xA0, a0); a1 = ffma2(wA0[2 * k + 1], xA1, a1);
            a2 = ffma2(wA1[2 * k], xA0, a2); a3 = ffma2(wA1[2 * k + 1], xA1, a3);
            b0 = ffma2(wB0[2 * k], xB0, b0); b1 = ffma2(wB0[2 * k + 1], xB1, b1);
            b2 = ffma2(wB1[2 * k], xB0, b2); b3 = ffma2(wB1[2 * k + 1], xB1, b3);
        }
        float eA0 = hsum(fadd2(a0, a1)) + s->ba[iA * 64 + c0];
        float eA1 = hsum(fadd2(a2, a3)) + s->ba[iA * 64 + c1];
        float eB0 = hsum(fadd2(b0, b1)) + s->ba[iB * 64 + c0];
        float eB1 = hsum(fadd2(b2, b3)) + s->ba[iB * 64 + c1];
        float vA = tanh_mufu(eA0) * s->va[iA * 64 + c0]
                 + tanh_mufu(eA1) * s->va[iA * 64 + c1];
        float vB = tanh_mufu(eB0) * s->va[iB * 64 + c0]
                 + tanh_mufu(eB1) * s->va[iB * 64 + c1];
#pragma unroll
        for (int off = 16; off; off >>= 1) {
            vA += __shfl_xor_sync(FULL, vA, off);
            vB += __shfl_xor_sync(FULL, vB, off);
        }
        if (lane == 0) { s->e[iA * 6 + lA] = vA; s->e[iB * 6 + lB] = vB; }
    };

    // =========================== time loop ===========================
    for (int t = 0; t < T_STEPS; t++) {
        // -------- Phase A1: warp 0, layers 0..3 --------
        if (warp == 0) {
            if (lane < 12 && (t + 1) < T_STEPS)
                cp_async16(&s->gi0[((t + 1) & 1) * GD + lane * 4],
                           &g_GI0[(t + 1) * GD + lane * 4]);
            asm volatile("cp.async.commit_group;\n");
            asm volatile("cp.async.wait_group 1;\n");
            __syncwarp();

            const float* g = &s->gi0[(t & 1) * GD];
            // layer 0 (gi precomputed incl b_ih0)
            {
                float ap = g[lane] + s->ghP[lane];
                float gv = sigmoid_mufu(ap);
                float zv = __shfl_sync(FULL, gv, 16 + jlow);
                float an = g[32 + jlow] + gv * s->ghN[jlow];
                float n  = tanh_mufu(an);
                float hp = s->h[jlow];
                float newh = n + zv * (hp - n);
                if (lane < 16) s->newS[lane] = newh;
                __syncwarp();
            }
            gru_layer(1);
            gru_layer(2);
            gru_layer(3);
        }
        __syncthreads();   // newS[0..3] visible

        // -------- Phase A2 (warp0: layers 4..5) || E-early (warps 1..5) --------
        if (warp == 0) {
            gru_layer(4);
            gru_layer(5);
        } else if (warp <= 5) {
            const int p = (warp - 1) * 2;
            energy2(c_PIE[p], c_PLE[p], c_PIE[p + 1], c_PLE[p + 1]);
        }
        __syncthreads();   // newS[4..5] + early e visible

        // -------- Phase F: fused late-energies + softmax + combine + gh ------
        // warp i (i<5): compute e[i][4], e[i][5] in-register, softmax over
        // {e[i][i..3] (smem), vA, vB}, combine, gh. warp5: copy+gh. warp6: FC.
        if (warp < 5) {
            const int i = warp;
            const ull* ip4 = (const ull*)&s->newS[4 * 16];
            const ull* ip5 = (const ull*)&s->newS[5 * 16];
            const int c0 = lane, c1 = lane + 32;
            const ull* w0 = (const ull*)&s->Wac[(i * 64 + c0) * 18];
            const ull* w1 = (const ull*)&s->Wac[(i * 64 + c1) * 18];
            ull a0 = 0ull, a1 = 0ull, a2 = 0ull, a3 = 0ull;
            ull b0 = 0ull, b1 = 0ull, b2 = 0ull, b3 = 0ull;
#pragma unroll
            for (int k = 0; k < 4; k++) {
                ull x40 = ip4[2 * k], x41 = ip4[2 * k + 1];
                ull x50 = ip5[2 * k], x51 = ip5[2 * k + 1];
                a0 = ffma2(w0[2 * k], x40, a0); a1 = ffma2(w0[2 * k + 1], x41, a1);
                a2 = ffma2(w1[2 * k], x40, a2); a3 = ffma2(w1[2 * k + 1], x41, a3);
                b0 = ffma2(w0[2 * k], x50, b0); b1 = ffma2(w0[2 * k + 1], x51, b1);
                b2 = ffma2(w1[2 * k], x50, b2); b3 = ffma2(w1[2 * k + 1], x51, b3);
            }
            float bac0 = s->ba[i * 64 + c0], bac1 = s->ba[i * 64 + c1];
            float vac0 = s->va[i * 64 + c0], vac1 = s->va[i * 64 + c1];
            float vA = tanh_mufu(hsum(fadd2(a0, a1)) + bac0) * vac0
                     + tanh_mufu(hsum(fadd2(a2, a3)) + bac1) * vac1;
            float vB = tanh_mufu(hsum(fadd2(b0, b1)) + bac0) * vac0
                     + tanh_mufu(hsum(fadd2(b2, b3)) + bac1) * vac1;
#pragma unroll
            for (int off = 16; off; off >>= 1) {
                vA += __shfl_xor_sync(FULL, vA, off);
                vB += __shfl_xor_sync(FULL, vB, off);
            }
            // softmax over k = 6-i energies: [i..3] from smem, then vA, vB
            const int k = 6 - i;
            float ev[6], wv[6];
            for (int q = 0; q < 4 - i; q++) ev[q] = s->e[i * 6 + i + q];
            ev[4 - i] = vA; ev[5 - i] = vB;
            float m = -1e30f;
            for (int q = 0; q < k; q++) m = fmaxf(m, ev[q]);
            float ssum = 0.f;
            for (int q = 0; q < k; q++) { wv[q] = __expf(ev[q] - m); ssum += wv[q]; }
            float inv = __fdividef(1.f, ssum);
            if (lane < 16) {
                float acc = 0.f;
                for (int q = 0; q < k; q++)
                    acc += wv[q] * s->newS[(i + q) * 16 + lane];
                s->h[i * 16 + lane] = acc * inv;
            }
            __syncwarp();
            gh_update(i);
        } else if (warp == 5) {
            if (lane < 16) s->h[5 * 16 + lane] = s->newS[5 * 16 + lane];
            __syncwarp();
            gh_update(5);
        } else if (warp == 6) {
            const ull* ip = (const ull*)&s->newS[5 * 16];
            const ull* fw = (const ull*)&s->fc1r[lane * 20];
            ull a0 = 0ull, a1 = 0ull;
#pragma unroll
            for (int k = 0; k < 4; k++) {
                a0 = ffma2(fw[2 * k], ip[2 * k], a0);
                a1 = ffma2(fw[2 * k + 1], ip[2 * k + 1], a1);
            }
            float acc = (hsum(fadd2(a0, a1)) + s->fc1b[lane]) * s->fc2[lane];
#pragma unroll
            for (int off = 16; off; off >>= 1)
                acc += __shfl_xor_sync(FULL, acc, off);
            if (lane == 0) out[t] = acc + s->fc2b;
        }
        __syncthreads();   // h, ghP, ghN ready for next step
    }
}

// ---------------------------------------------------------------------------
extern "C" void kernel_launch(void* const* d_in, const int* in_sizes, int n_in,
                              void* d_out, int out_size)
{
    const float* batch  = (const float*)d_in[0];
    const float* h0     = (const float*)d_in[1];
    const float* W_ih0  = (const float*)d_in[2];
    const float* W_hh0  = (const float*)d_in[3];
    const float* b_ih0  = (const float*)d_in[4];
    const float* b_hh0  = (const float*)d_in[5];
    const float* W_ih   = (const float*)d_in[6];
    const float* W_hh   = (const float*)d_in[7];
    const float* b_ih   = (const float*)d_in[8];
    const float* b_hh   = (const float*)d_in[9];
    const float* Wa     = (const float*)d_in[10];
    const float* ba     = (const float*)d_in[11];
    const float* va     = (const float*)d_in[12];
    const float* fc1_w  = (const float*)d_in[13];
    const float* fc1_b  = (const float*)d_in[14];
    const float* fc2_w  = (const float*)d_in[15];
    const float* fc2_b  = (const float*)d_in[16];
    float* out = (float*)d_out;

    cudaFuncSetAttribute(k_scan, cudaFuncAttributeMaxDynamicSharedMemorySize,
                         (int)sizeof(Smem));

    k_gi0<<<T_STEPS / 32, 256>>>(batch, W_ih0, b_ih0);
    k_scan<<<1, 256, sizeof(Smem)>>>(h0, W_hh0, b_hh0, W_ih, W_hh, b_ih, b_hh,
                                     Wa, ba, va, fc1_w, fc1_b, fc2_w, fc2_b, out);
}